// round 1
// baseline (speedup 1.0000x reference)
#include <cuda_runtime.h>

// Problem constants
// arr_batch: [4,16,16,16,16,32] f32, M: [32,32], Acoeff: [32,81], Bbasis: [81,32]
// out: [4,32] f32
#define BSZ 4
#define D 16
#define MDIM 32
#define LTOT 81

// Scratch (no cudaMalloc allowed): Q[b][p1][p2][j3][j4][m]
__device__ float g_Q[BSZ * D * D * 9 * MDIM];   // 4.7 MB
__device__ float g_H[BSZ * LTOT];               // 324 floats

// ---------------------------------------------------------------------------
// Pass 1: block (b,p1,p2) streams arr[b,p1,p2,:,:,:] (16x16x32 = 32KB),
// contracts p3 (in registers) and p4 (via shared) into Q[b,p1,p2,j3,j4,m].
// w[p][j]: p contributes to j=(p-1)%3 (if p>=1) and j=p%3 (if p<=14).
// ---------------------------------------------------------------------------
__global__ void __launch_bounds__(512) pass1_kernel(const float* __restrict__ arr) {
    __shared__ float S[16][3][32];   // [p4][j3][m]

    const int b  = blockIdx.z;
    const int p1 = blockIdx.y;
    const int p2 = blockIdx.x;
    const int t  = threadIdx.x;
    const int m  = t & 31;
    const int p4 = t >> 5;

    const float* __restrict__ src =
        arr + ((size_t)((b * D + p1) * D + p2)) * (D * D * MDIM) + p4 * MDIM + m;

    float acc0 = 0.f, acc1 = 0.f, acc2 = 0.f;
#pragma unroll
    for (int p3 = 0; p3 < 16; ++p3) {
        float v = src[p3 * (D * MDIM)];
        if (p3 >= 1) {
            const int ja = (p3 - 1) % 3;
            if (ja == 0) acc0 += v; else if (ja == 1) acc1 += v; else acc2 += v;
        }
        if (p3 <= 14) {
            const int jb = p3 % 3;
            if (jb == 0) acc0 += v; else if (jb == 1) acc1 += v; else acc2 += v;
        }
    }
    S[p4][0][m] = acc0;
    S[p4][1][m] = acc1;
    S[p4][2][m] = acc2;
    __syncthreads();

    if (t < 288) {
        const int m2 = t & 31;
        const int g  = t >> 5;      // 0..8
        const int j4 = g % 3;
        const int j3 = g / 3;
        float q = 0.f;
        // P(j) = {3k + j, 3k + j + 1 : k = 0..4}, always 10 positions
#pragma unroll
        for (int i = 0; i < 10; ++i) {
            const int p = 3 * (i >> 1) + j4 + (i & 1);
            q += S[p][j3][m2];
        }
        g_Q[((((b * D + p1) * D + p2) * 9) + j3 * 3 + j4) * MDIM + m2] = q;
    }
}

// ---------------------------------------------------------------------------
// Pass 2: block (c, b) computes H[b,c] = sum_m E[c,m] * G[b,c,m]
//   E[c,m]   = sum_n Bbasis[c,n] * M[n,m]
//   G[b,c,m] = sum over 100 (p1,p2) pairs of Q[b,p1,p2,j3,j4,m]
// ---------------------------------------------------------------------------
__global__ void __launch_bounds__(128) pass2_kernel(const float* __restrict__ Mmat,
                                                    const float* __restrict__ Bbasis) {
    __shared__ float E_s[32];
    __shared__ float part[4][32];

    const int c  = blockIdx.x;   // 0..80
    const int b  = blockIdx.y;   // 0..3
    const int t  = threadIdx.x;
    const int lane = t & 31;
    const int wp   = t >> 5;

    const int j4 = c % 3;
    const int j3 = (c / 3) % 3;
    const int j2 = (c / 9) % 3;
    const int j1 = c / 27;
    const int jj = j3 * 3 + j4;

    if (t < 32) {
        float e = 0.f;
#pragma unroll
        for (int n = 0; n < 32; ++n)
            e += Bbasis[c * MDIM + n] * Mmat[n * MDIM + t];
        E_s[t] = e;
    }

    const float* __restrict__ Qb = g_Q + (size_t)b * (D * D * 9 * MDIM);
    float g = 0.f;
    for (int k = wp; k < 100; k += 4) {
        const int a  = k / 10;
        const int dd = k % 10;
        const int p1 = 3 * (a >> 1) + j1 + (a & 1);
        const int p2 = 3 * (dd >> 1) + j2 + (dd & 1);
        g += Qb[(((p1 * D + p2) * 9) + jj) * MDIM + lane];
    }
    part[wp][lane] = g;
    __syncthreads();

    if (wp == 0) {
        float G = part[0][lane] + part[1][lane] + part[2][lane] + part[3][lane];
        float h = E_s[lane] * G;
#pragma unroll
        for (int off = 16; off > 0; off >>= 1)
            h += __shfl_xor_sync(0xffffffffu, h, off);
        if (lane == 0) g_H[b * LTOT + c] = h;
    }
}

// ---------------------------------------------------------------------------
// Pass 3: out[b,n] = K * sum_c H[b,c] * Acoeff[n,c],  K = 1/(16 * 15^4)
// ---------------------------------------------------------------------------
__global__ void __launch_bounds__(128) pass3_kernel(const float* __restrict__ Acoeff,
                                                    float* __restrict__ out) {
    const int t = threadIdx.x;
    if (t >= 128) return;
    const int b = t >> 5;
    const int n = t & 31;
    const float K = 1.0f / (16.0f * 50625.0f);
    float s = 0.f;
#pragma unroll
    for (int c = 0; c < LTOT; ++c)
        s += g_H[b * LTOT + c] * Acoeff[n * LTOT + c];
    out[b * MDIM + n] = s * K;
}

extern "C" void kernel_launch(void* const* d_in, const int* in_sizes, int n_in,
                              void* d_out, int out_size) {
    const float* arr    = (const float*)d_in[0];  // [4,16,16,16,16,32]
    const float* Mmat   = (const float*)d_in[1];  // [32,32]
    const float* Acoeff = (const float*)d_in[2];  // [32,81]
    const float* Bbasis = (const float*)d_in[3];  // [81,32]
    float* out = (float*)d_out;                   // [4,32]

    dim3 g1(D, D, BSZ);          // (p2, p1, b)
    pass1_kernel<<<g1, 512>>>(arr);

    dim3 g2(LTOT, BSZ);          // (c, b)
    pass2_kernel<<<g2, 128>>>(Mmat, Bbasis);

    pass3_kernel<<<1, 128>>>(Acoeff, out);
}